// round 14
// baseline (speedup 1.0000x reference)
#include <cuda_runtime.h>
#include <cstdint>

#define NN 20000
#define EE 320000
#define CC 128
#define BB 20
#define RCUT_F 5.0f
#define EPS_F 1e-8f

// ---------------- scratch (device globals; no allocation allowed) ----------------
__device__ float g_x  [NN * 3 * CC];   // per-node context net output [N,3C]
__device__ float g_q1 [NN * CC];       // q + dq (accumulated)
__device__ float g_mu1[NN * 3 * CC];   // mu + dmu (accumulated)
__device__ float g_muV[NN * 3 * CC];
__device__ float g_muW[NN * 3 * CC];
// CSR for receiver-major edge traversal
__device__ int g_cnt[NN];
__device__ int g_off[NN + 1];
__device__ int g_cur[NN];
__device__ int g_perm[EE];

// ---------------- helpers ----------------
__device__ __forceinline__ float siluf(float x) {
    return x * (1.0f / (1.0f + __expf(-x)));
}
// packed fp32x2 FMA (Blackwell FFMA2): d = a*b + d
__device__ __forceinline__ void fma2(uint64_t& d, uint64_t a, uint64_t b) {
    asm("fma.rn.f32x2 %0, %1, %2, %0;" : "+l"(d) : "l"(a), "l"(b));
}
__device__ __forceinline__ uint64_t pk(float lo, float hi) {
    uint64_t r; asm("mov.b64 %0, {%1, %2};" : "=l"(r) : "f"(lo), "f"(hi)); return r;
}
__device__ __forceinline__ uint64_t bcast2(float w) {
    uint64_t r; asm("mov.b64 %0, {%1, %1};" : "=l"(r) : "f"(w)); return r;
}
__device__ __forceinline__ float2 unpk(uint64_t p) {
    float2 r; asm("mov.b64 {%0, %1}, %2;" : "=f"(r.x), "=f"(r.y) : "l"(p)); return r;
}
// cp.async (LDGSTS): zero-register weight staging
__device__ __forceinline__ void cpa16(uint32_t dst, const float* src) {
    asm volatile("cp.async.cg.shared.global [%0], [%1], 16;" :: "r"(dst), "l"(src));
}
#define CP_COMMIT() asm volatile("cp.async.commit_group;" ::: "memory")
#define CP_WAIT0()  asm volatile("cp.async.wait_group 0;" ::: "memory")

// Node-GEMV tiling (proven R11 shape): 256 threads, 16 nodes/block.
#define NPB 16
#define NH  8
#define STR 20   // padded tile row stride in floats

// ============================================================================
// CSR build: histogram -> scan -> permutation
// ============================================================================
__global__ void k_zero() {
    int t = blockIdx.x * blockDim.x + threadIdx.x;
    if (t < NN) g_cnt[t] = 0;
}
__global__ void k_hist(const int* __restrict__ eidx) {
    int e = blockIdx.x * blockDim.x + threadIdx.x;
    if (e < EE) atomicAdd(&g_cnt[eidx[e]], 1);
}
#define SCAN_T 1024
#define SCAN_R 20   // 1024*20 = 20480 >= NN
__global__ __launch_bounds__(SCAN_T) void k_scan() {
    __shared__ int part[SCAN_T];
    const int t = threadIdx.x;
    int local[SCAN_R];
    int s = 0;
    #pragma unroll
    for (int r = 0; r < SCAN_R; r++) {
        int idx = t * SCAN_R + r;
        int c = (idx < NN) ? g_cnt[idx] : 0;
        local[r] = s;
        s += c;
    }
    part[t] = s;
    __syncthreads();
    // inclusive Hillis-Steele scan over 1024 partials
    for (int off = 1; off < SCAN_T; off <<= 1) {
        int v = (t >= off) ? part[t - off] : 0;
        __syncthreads();
        part[t] += v;
        __syncthreads();
    }
    const int excl = part[t] - s;
    #pragma unroll
    for (int r = 0; r < SCAN_R; r++) {
        int idx = t * SCAN_R + r;
        if (idx < NN) {
            int o = excl + local[r];
            g_off[idx] = o;
            g_cur[idx] = o;
        }
    }
    if (t == SCAN_T - 1) g_off[NN] = part[SCAN_T - 1];
}
__global__ void k_perm(const int* __restrict__ eidx) {
    int e = blockIdx.x * blockDim.x + threadIdx.x;
    if (e < EE) {
        int pos = atomicAdd(&g_cur[eidx[e]], 1);
        g_perm[pos] = e;
    }
}

// ============================================================================
// K1: context net  x = silu(q@W1+b1)@W2+b2 ; seed g_q1=q, g_mu1=mu  (R11 shape)
// ============================================================================
#define K1R1 16
#define K1T1 (CC / K1R1)
#define K1R2 8
#define K1T2 (CC / K1R2)

__global__ __launch_bounds__(256) void k_context(
    const float* __restrict__ q, const float* __restrict__ mu,
    const float* __restrict__ W1, const float* __restrict__ b1,
    const float* __restrict__ W2, const float* __restrict__ b2)
{
    __shared__ __align__(16) float sqT[CC * STR];
    __shared__ __align__(16) float shT[CC * STR];
    __shared__ __align__(16) float sW[2][3 * CC * K1R2];
    const int tid  = threadIdx.x;
    const int d    = tid & 127;
    const int h    = tid >> 7;
    const int base = blockIdx.x * NPB;
    const uint32_t swb0 = (uint32_t)__cvta_generic_to_shared(sW[0]);
    const uint32_t swb1 = (uint32_t)__cvta_generic_to_shared(sW[1]);

    #pragma unroll
    for (int n2 = 0; n2 < NH; n2++) {
        const int n = n2 * 2 + h;
        float v = q[(base + n) * CC + d];
        sqT[d * STR + n] = v;
        g_q1[(base + n) * CC + d] = v;
    }
    {
        const float4* src = reinterpret_cast<const float4*>(&mu[base * 3 * CC]);
        float4* dst = reinterpret_cast<float4*>(&g_mu1[base * 3 * CC]);
        #pragma unroll
        for (int t = tid; t < NPB * 3 * CC / 4; t += 256) dst[t] = src[t];
    }
    __syncthreads();

    uint64_t acc[4];
    {
        float bb = b1[d];
        uint64_t bi = pk(bb, bb);
        #pragma unroll
        for (int m = 0; m < 4; m++) acc[m] = bi;

        #pragma unroll
        for (int t = tid; t < K1R1 * CC / 4; t += 256)
            cpa16(swb0 + t * 16, W1 + t * 4);
        CP_COMMIT();

        for (int kt = 0; kt < K1T1; kt++) {
            CP_WAIT0();
            __syncthreads();
            if (kt + 1 < K1T1) {
                const float* src = W1 + (kt + 1) * K1R1 * CC;
                uint32_t dstb = ((kt + 1) & 1) ? swb1 : swb0;
                #pragma unroll
                for (int t = tid; t < K1R1 * CC / 4; t += 256)
                    cpa16(dstb + t * 16, src + t * 4);
                CP_COMMIT();
            }
            const float* sWt = sW[kt & 1];
            #pragma unroll
            for (int r = 0; r < K1R1; r++) {
                const int k = kt * K1R1 + r;
                uint64_t ww = bcast2(sWt[r * CC + d]);
                const ulonglong2* row = reinterpret_cast<const ulonglong2*>(&sqT[k * STR + h * NH]);
                ulonglong2 v0 = row[0], v1 = row[1];
                fma2(acc[0], v0.x, ww); fma2(acc[1], v0.y, ww);
                fma2(acc[2], v1.x, ww); fma2(acc[3], v1.y, ww);
            }
        }
    }
    __syncthreads();
    #pragma unroll
    for (int m = 0; m < 4; m++) {
        float2 p = unpk(acc[m]);
        shT[d * STR + h * NH + 2*m]     = siluf(p.x);
        shT[d * STR + h * NH + 2*m + 1] = siluf(p.y);
    }
    __syncthreads();

    {
        uint64_t a2[3][4];
        #pragma unroll
        for (int g = 0; g < 3; g++) {
            float bb = b2[g * CC + d];
            uint64_t bi = pk(bb, bb);
            #pragma unroll
            for (int m = 0; m < 4; m++) a2[g][m] = bi;
        }
        #pragma unroll
        for (int t = tid; t < K1R2 * 3 * CC / 4; t += 256)
            cpa16(swb0 + t * 16, W2 + t * 4);
        CP_COMMIT();

        for (int kt = 0; kt < K1T2; kt++) {
            CP_WAIT0();
            __syncthreads();
            if (kt + 1 < K1T2) {
                const float* src = W2 + (kt + 1) * K1R2 * 3 * CC;
                uint32_t dstb = ((kt + 1) & 1) ? swb1 : swb0;
                #pragma unroll
                for (int t = tid; t < K1R2 * 3 * CC / 4; t += 256)
                    cpa16(dstb + t * 16, src + t * 4);
                CP_COMMIT();
            }
            const float* sWt = sW[kt & 1];
            #pragma unroll
            for (int r = 0; r < K1R2; r++) {
                const int k = kt * K1R2 + r;
                uint64_t w0 = bcast2(sWt[r * 3 * CC + 0 * CC + d]);
                uint64_t w1 = bcast2(sWt[r * 3 * CC + 1 * CC + d]);
                uint64_t w2 = bcast2(sWt[r * 3 * CC + 2 * CC + d]);
                const ulonglong2* row = reinterpret_cast<const ulonglong2*>(&shT[k * STR + h * NH]);
                ulonglong2 v0 = row[0], v1 = row[1];
                fma2(a2[0][0], v0.x, w0); fma2(a2[0][1], v0.y, w0);
                fma2(a2[0][2], v1.x, w0); fma2(a2[0][3], v1.y, w0);
                fma2(a2[1][0], v0.x, w1); fma2(a2[1][1], v0.y, w1);
                fma2(a2[1][2], v1.x, w1); fma2(a2[1][3], v1.y, w1);
                fma2(a2[2][0], v0.x, w2); fma2(a2[2][1], v0.y, w2);
                fma2(a2[2][2], v1.x, w2); fma2(a2[2][3], v1.y, w2);
            }
        }
        #pragma unroll
        for (int g = 0; g < 3; g++) {
            #pragma unroll
            for (int m = 0; m < 4; m++) {
                float2 p = unpk(a2[g][m]);
                g_x[(base + h * NH + 2*m)     * 3 * CC + g * CC + d] = p.x;
                g_x[(base + h * NH + 2*m + 1) * 3 * CC + g * CC + d] = p.y;
            }
        }
    }
}

// ============================================================================
// K2: edge kernel, GATHER form. One warp per receiver node; loops its CSR
// segment, accumulates dq/dmu in registers, single exclusive write-back.
// No atomics. Wf staged in smem; filter GEMV in FFMA2.
// ============================================================================
__global__ __launch_bounds__(256) void k_edge_g(
    const int*   __restrict__ eidx,     // [2,E]
    const float* __restrict__ ew,       // [E]
    const float* __restrict__ evs,      // [E,3]
    const float* __restrict__ attrs,    // [E,B]
    const float* __restrict__ Wf,       // [B,3C]
    const float* __restrict__ bf,       // [3C]
    const float* __restrict__ mu)       // [N,3,C]
{
    __shared__ __align__(16) float sWf[BB * 3 * CC];
    __shared__ __align__(16) float sbf[3 * CC];

    for (int t = threadIdx.x; t < BB * 3 * CC / 4; t += 256)
        reinterpret_cast<float4*>(sWf)[t] = reinterpret_cast<const float4*>(Wf)[t];
    for (int t = threadIdx.x; t < 3 * CC / 4; t += 256)
        reinterpret_cast<float4*>(sbf)[t] = reinterpret_cast<const float4*>(bf)[t];
    __syncthreads();

    const int lane = threadIdx.x & 31;
    const int wid  = threadIdx.x >> 5;
    const int c0   = lane * 4;
    const int i    = blockIdx.x * 8 + wid;   // receiver node (grid = NN/8)

    const float4 bq = *reinterpret_cast<const float4*>(&sbf[c0]);
    const float4 bR = *reinterpret_cast<const float4*>(&sbf[CC + c0]);
    const float4 bm = *reinterpret_cast<const float4*>(&sbf[2 * CC + c0]);

    const int kbeg = g_off[i];
    const int kend = g_off[i + 1];

    float4 aq  = make_float4(0.f, 0.f, 0.f, 0.f);
    float4 am0 = make_float4(0.f, 0.f, 0.f, 0.f);
    float4 am1 = make_float4(0.f, 0.f, 0.f, 0.f);
    float4 am2 = make_float4(0.f, 0.f, 0.f, 0.f);

    for (int kk = kbeg; kk < kend; kk++) {
        const int e = g_perm[kk];
        const int j = eidx[EE + e];
        const float wdist = ew[e];
        const float f = (wdist < RCUT_F)
            ? 0.5f * (__cosf((3.14159265358979f / RCUT_F) * wdist) + 1.0f) : 0.0f;

        float av = (lane < BB) ? attrs[e * BB + lane] : 0.0f;
        float vv = (lane < 3)  ? evs[e * 3 + lane]    : 0.0f;
        const float ev0 = __shfl_sync(0xFFFFFFFFu, vv, 0);
        const float ev1 = __shfl_sync(0xFFFFFFFFu, vv, 1);
        const float ev2 = __shfl_sync(0xFFFFFFFFu, vv, 2);

        uint64_t acc0 = pk(bq.x, bq.y), acc1 = pk(bq.z, bq.w);
        uint64_t acc2 = pk(bR.x, bR.y), acc3 = pk(bR.z, bR.w);
        uint64_t acc4 = pk(bm.x, bm.y), acc5 = pk(bm.z, bm.w);

        #pragma unroll
        for (int b = 0; b < BB; b++) {
            uint64_t aw = bcast2(__shfl_sync(0xFFFFFFFFu, av, b));
            ulonglong2 f0 = *reinterpret_cast<const ulonglong2*>(&sWf[b * 3 * CC + c0]);
            ulonglong2 f1 = *reinterpret_cast<const ulonglong2*>(&sWf[b * 3 * CC + CC + c0]);
            ulonglong2 f2 = *reinterpret_cast<const ulonglong2*>(&sWf[b * 3 * CC + 2 * CC + c0]);
            fma2(acc0, f0.x, aw); fma2(acc1, f0.y, aw);
            fma2(acc2, f1.x, aw); fma2(acc3, f1.y, aw);
            fma2(acc4, f2.x, aw); fma2(acc5, f2.y, aw);
        }

        float2 wq0 = unpk(acc0), wq1 = unpk(acc1);
        float2 wR0 = unpk(acc2), wR1 = unpk(acc3);
        float2 wm0 = unpk(acc4), wm1 = unpk(acc5);

        const float4* xb = reinterpret_cast<const float4*>(&g_x[j * 3 * CC]);
        float4 x0 = xb[lane];
        float4 x1 = xb[32 + lane];
        float4 x2 = xb[64 + lane];

        aq.x = fmaf(x0.x, wq0.x * f, aq.x);
        aq.y = fmaf(x0.y, wq0.y * f, aq.y);
        aq.z = fmaf(x0.z, wq1.x * f, aq.z);
        aq.w = fmaf(x0.w, wq1.y * f, aq.w);

        float4 cR = make_float4(x1.x * wR0.x * f, x1.y * wR0.y * f,
                                x1.z * wR1.x * f, x1.w * wR1.y * f);
        float4 cm = make_float4(x2.x * wm0.x * f, x2.y * wm0.y * f,
                                x2.z * wm1.x * f, x2.w * wm1.y * f);

        const float4* mub = reinterpret_cast<const float4*>(&mu[j * 3 * CC]);
        float4 mj0 = mub[lane];
        float4 mj1 = mub[32 + lane];
        float4 mj2 = mub[64 + lane];

        am0.x = fmaf(cm.x, mj0.x, fmaf(cR.x, ev0, am0.x));
        am0.y = fmaf(cm.y, mj0.y, fmaf(cR.y, ev0, am0.y));
        am0.z = fmaf(cm.z, mj0.z, fmaf(cR.z, ev0, am0.z));
        am0.w = fmaf(cm.w, mj0.w, fmaf(cR.w, ev0, am0.w));
        am1.x = fmaf(cm.x, mj1.x, fmaf(cR.x, ev1, am1.x));
        am1.y = fmaf(cm.y, mj1.y, fmaf(cR.y, ev1, am1.y));
        am1.z = fmaf(cm.z, mj1.z, fmaf(cR.z, ev1, am1.z));
        am1.w = fmaf(cm.w, mj1.w, fmaf(cR.w, ev1, am1.w));
        am2.x = fmaf(cm.x, mj2.x, fmaf(cR.x, ev2, am2.x));
        am2.y = fmaf(cm.y, mj2.y, fmaf(cR.y, ev2, am2.y));
        am2.z = fmaf(cm.z, mj2.z, fmaf(cR.z, ev2, am2.z));
        am2.w = fmaf(cm.w, mj2.w, fmaf(cR.w, ev2, am2.w));
    }

    // exclusive write-back: g_q1 = q + dq ; g_mu1 = mu + dmu
    {
        float4* qp = reinterpret_cast<float4*>(&g_q1[i * CC + c0]);
        float4 o = *qp;
        *qp = make_float4(o.x + aq.x, o.y + aq.y, o.z + aq.z, o.w + aq.w);
        float4* m0 = reinterpret_cast<float4*>(&g_mu1[(i * 3 + 0) * CC + c0]);
        float4* m1 = reinterpret_cast<float4*>(&g_mu1[(i * 3 + 1) * CC + c0]);
        float4* m2 = reinterpret_cast<float4*>(&g_mu1[(i * 3 + 2) * CC + c0]);
        float4 o0 = *m0, o1 = *m1, o2 = *m2;
        *m0 = make_float4(o0.x + am0.x, o0.y + am0.y, o0.z + am0.z, o0.w + am0.w);
        *m1 = make_float4(o1.x + am1.x, o1.y + am1.y, o1.z + am1.z, o1.w + am1.w);
        *m2 = make_float4(o2.x + am2.x, o2.y + am2.y, o2.z + am2.z, o2.w + am2.w);
    }
}

// ============================================================================
// K3a: mu_mix = mu1 @ W_mix -> muV, muW.  (R11 shape)
// ============================================================================
#define K3R 8
#define K3T (CC / K3R)

__global__ __launch_bounds__(256) void k_mumix(const float* __restrict__ Wmix)
{
    __shared__ __align__(16) float sT[CC * STR];
    __shared__ __align__(16) float sW[2][K3R * 2 * CC];
    const int tid  = threadIdx.x;
    const int d    = tid & 127;
    const int h    = tid >> 7;
    const int base = blockIdx.x * NPB;
    const uint32_t swb0 = (uint32_t)__cvta_generic_to_shared(sW[0]);
    const uint32_t swb1 = (uint32_t)__cvta_generic_to_shared(sW[1]);

    #pragma unroll
    for (int n2 = 0; n2 < NH; n2++) {
        const int r = n2 * 2 + h;
        sT[d * STR + r] = g_mu1[(base + r) * CC + d];
    }
    __syncthreads();

    uint64_t acc[2][4];
    #pragma unroll
    for (int g = 0; g < 2; g++)
        #pragma unroll
        for (int m = 0; m < 4; m++) acc[g][m] = 0ull;

    #pragma unroll
    for (int t = tid; t < K3R * 2 * CC / 4; t += 256)
        cpa16(swb0 + t * 16, Wmix + t * 4);
    CP_COMMIT();

    for (int kt = 0; kt < K3T; kt++) {
        CP_WAIT0();
        __syncthreads();
        if (kt + 1 < K3T) {
            const float* src = Wmix + (kt + 1) * K3R * 2 * CC;
            uint32_t dstb = ((kt + 1) & 1) ? swb1 : swb0;
            #pragma unroll
            for (int t = tid; t < K3R * 2 * CC / 4; t += 256)
                cpa16(dstb + t * 16, src + t * 4);
            CP_COMMIT();
        }
        const float* sWt = sW[kt & 1];
        #pragma unroll
        for (int r = 0; r < K3R; r++) {
            const int k = kt * K3R + r;
            uint64_t w0 = bcast2(sWt[r * 2 * CC + 0 * CC + d]);
            uint64_t w1 = bcast2(sWt[r * 2 * CC + 1 * CC + d]);
            const ulonglong2* row = reinterpret_cast<const ulonglong2*>(&sT[k * STR + h * NH]);
            ulonglong2 v0 = row[0], v1 = row[1];
            fma2(acc[0][0], v0.x, w0); fma2(acc[0][1], v0.y, w0);
            fma2(acc[0][2], v1.x, w0); fma2(acc[0][3], v1.y, w0);
            fma2(acc[1][0], v0.x, w1); fma2(acc[1][1], v0.y, w1);
            fma2(acc[1][2], v1.x, w1); fma2(acc[1][3], v1.y, w1);
        }
    }
    #pragma unroll
    for (int g = 0; g < 2; g++) {
        float* dst = (g == 0) ? g_muV : g_muW;
        #pragma unroll
        for (int m = 0; m < 4; m++) {
            float2 p = unpk(acc[g][m]);
            dst[(base + h * NH + 2*m)     * CC + d] = p.x;
            dst[(base + h * NH + 2*m + 1) * CC + d] = p.y;
        }
    }
}

// ============================================================================
// K3b: mixing MLP + final outputs.  (R11 shape)
// ============================================================================
#define K4R1 16
#define K4T1 (2 * CC / K4R1)
#define K4R2 8
#define K4T2 (CC / K4R2)

__global__ __launch_bounds__(256) void k_mixout(
    const float* __restrict__ Wm1, const float* __restrict__ bm1,
    const float* __restrict__ Wm2, const float* __restrict__ bm2,
    float* __restrict__ out_q, float* __restrict__ out_mu)
{
    __shared__ __align__(16) float buf[2 * CC * STR];
    __shared__ __align__(16) float sscal[NPB * CC];
    __shared__ __align__(16) float sW[2][3 * CC * K4R2];
    const int tid  = threadIdx.x;
    const int d    = tid & 127;
    const int h    = tid >> 7;
    const int base = blockIdx.x * NPB;
    const uint32_t swb0 = (uint32_t)__cvta_generic_to_shared(sW[0]);
    const uint32_t swb1 = (uint32_t)__cvta_generic_to_shared(sW[1]);

    #pragma unroll
    for (int n2 = 0; n2 < NH; n2++) {
        const int n = n2 * 2 + h;
        const int node = base + n;
        float q1v = g_q1[node * CC + d];
        float v0 = g_muV[(node * 3 + 0) * CC + d];
        float v1 = g_muV[(node * 3 + 1) * CC + d];
        float v2 = g_muV[(node * 3 + 2) * CC + d];
        float w0 = g_muW[(node * 3 + 0) * CC + d];
        float w1 = g_muW[(node * 3 + 1) * CC + d];
        float w2 = g_muW[(node * 3 + 2) * CC + d];
        float vn = sqrtf(fmaf(v0, v0, fmaf(v1, v1, fmaf(v2, v2, EPS_F))));
        sscal[n * CC + d] = fmaf(v0, w0, fmaf(v1, w1, v2 * w2));
        buf[d * STR + n] = q1v;
        buf[(CC + d) * STR + n] = vn;
    }
    __syncthreads();

    uint64_t acc[4];
    {
        float bb = bm1[d];
        uint64_t bi = pk(bb, bb);
        #pragma unroll
        for (int m = 0; m < 4; m++) acc[m] = bi;

        #pragma unroll
        for (int t = tid; t < K4R1 * CC / 4; t += 256)
            cpa16(swb0 + t * 16, Wm1 + t * 4);
        CP_COMMIT();

        for (int kt = 0; kt < K4T1; kt++) {
            CP_WAIT0();
            __syncthreads();
            if (kt + 1 < K4T1) {
                const float* src = Wm1 + (kt + 1) * K4R1 * CC;
                uint32_t dstb = ((kt + 1) & 1) ? swb1 : swb0;
                #pragma unroll
                for (int t = tid; t < K4R1 * CC / 4; t += 256)
                    cpa16(dstb + t * 16, src + t * 4);
                CP_COMMIT();
            }
            const float* sWt = sW[kt & 1];
            #pragma unroll
            for (int r = 0; r < K4R1; r++) {
                const int k = kt * K4R1 + r;
                uint64_t ww = bcast2(sWt[r * CC + d]);
                const ulonglong2* row = reinterpret_cast<const ulonglong2*>(&buf[k * STR + h * NH]);
                ulonglong2 v0 = row[0], v1 = row[1];
                fma2(acc[0], v0.x, ww); fma2(acc[1], v0.y, ww);
                fma2(acc[2], v1.x, ww); fma2(acc[3], v1.y, ww);
            }
        }
    }
    __syncthreads();
    #pragma unroll
    for (int m = 0; m < 4; m++) {
        float2 p = unpk(acc[m]);
        buf[(CC + d) * STR + h * NH + 2*m]     = siluf(p.x);
        buf[(CC + d) * STR + h * NH + 2*m + 1] = siluf(p.y);
    }
    __syncthreads();

    uint64_t a[3][4];
    #pragma unroll
    for (int g = 0; g < 3; g++) {
        float bb = bm2[g * CC + d];
        uint64_t bi = pk(bb, bb);
        #pragma unroll
        for (int m = 0; m < 4; m++) a[g][m] = bi;
    }
    #pragma unroll
    for (int t = tid; t < K4R2 * 3 * CC / 4; t += 256)
        cpa16(swb0 + t * 16, Wm2 + t * 4);
    CP_COMMIT();

    for (int kt = 0; kt < K4T2; kt++) {
        CP_WAIT0();
        __syncthreads();
        if (kt + 1 < K4T2) {
            const float* src = Wm2 + (kt + 1) * K4R2 * 3 * CC;
            uint32_t dstb = ((kt + 1) & 1) ? swb1 : swb0;
            #pragma unroll
            for (int t = tid; t < K4R2 * 3 * CC / 4; t += 256)
                cpa16(dstb + t * 16, src + t * 4);
            CP_COMMIT();
        }
        const float* sWt = sW[kt & 1];
        #pragma unroll
        for (int r = 0; r < K4R2; r++) {
            const int k = kt * K4R2 + r;
            uint64_t w0 = bcast2(sWt[r * 3 * CC + 0 * CC + d]);
            uint64_t w1 = bcast2(sWt[r * 3 * CC + 1 * CC + d]);
            uint64_t w2 = bcast2(sWt[r * 3 * CC + 2 * CC + d]);
            const ulonglong2* row = reinterpret_cast<const ulonglong2*>(&buf[(CC + k) * STR + h * NH]);
            ulonglong2 v0 = row[0], v1 = row[1];
            fma2(a[0][0], v0.x, w0); fma2(a[0][1], v0.y, w0);
            fma2(a[0][2], v1.x, w0); fma2(a[0][3], v1.y, w0);
            fma2(a[1][0], v0.x, w1); fma2(a[1][1], v0.y, w1);
            fma2(a[1][2], v1.x, w1); fma2(a[1][3], v1.y, w1);
            fma2(a[2][0], v0.x, w2); fma2(a[2][1], v0.y, w2);
            fma2(a[2][2], v1.x, w2); fma2(a[2][3], v1.y, w2);
        }
    }

    #pragma unroll
    for (int m = 0; m < 4; m++) {
        float2 p0 = unpk(a[0][m]);
        float2 p1 = unpk(a[1][m]);
        float2 p2 = unpk(a[2][m]);
        #pragma unroll
        for (int t = 0; t < 2; t++) {
            const int n = h * NH + 2*m + t;
            const int node = base + n;
            float y0 = t ? p0.y : p0.x;
            float y1 = t ? p1.y : p1.x;
            float y2 = t ? p2.y : p2.x;
            float q1v  = buf[d * STR + n];
            float scal = sscal[n * CC + d];
            out_q[node * CC + d] = q1v + y0 + y2 * scal;
            #pragma unroll
            for (int v = 0; v < 3; v++) {
                float mw = g_muW[(node * 3 + v) * CC + d];
                float m1 = g_mu1[(node * 3 + v) * CC + d];
                out_mu[(node * 3 + v) * CC + d] = fmaf(y1, mw, m1);
            }
        }
    }
}

// ============================================================================
extern "C" void kernel_launch(void* const* d_in, const int* in_sizes, int n_in,
                              void* d_out, int out_size)
{
    const float* q     = (const float*)d_in[0];
    const float* mu    = (const float*)d_in[1];
    const int*   eidx  = (const int*)  d_in[2];
    const float* ew    = (const float*)d_in[3];
    const float* evs   = (const float*)d_in[4];
    const float* attrs = (const float*)d_in[5];
    const float* Wf    = (const float*)d_in[6];
    const float* bf    = (const float*)d_in[7];
    const float* W1    = (const float*)d_in[8];
    const float* b1    = (const float*)d_in[9];
    const float* W2    = (const float*)d_in[10];
    const float* b2    = (const float*)d_in[11];
    const float* Wmix  = (const float*)d_in[12];
    const float* Wm1   = (const float*)d_in[13];
    const float* bm1   = (const float*)d_in[14];
    const float* Wm2   = (const float*)d_in[15];
    const float* bm2   = (const float*)d_in[16];

    float* out_q  = (float*)d_out;
    float* out_mu = out_q + (size_t)NN * CC;

    // CSR build (receiver-major edge ordering)
    k_zero<<<(NN + 255) / 256, 256>>>();
    k_hist<<<(EE + 255) / 256, 256>>>(eidx);
    k_scan<<<1, SCAN_T>>>();
    k_perm<<<(EE + 255) / 256, 256>>>(eidx);

    k_context<<<NN / NPB, 256>>>(q, mu, W1, b1, W2, b2);
    k_edge_g<<<NN / 8, 256>>>(eidx, ew, evs, attrs, Wf, bf, mu);
    k_mumix<<<(3 * NN) / NPB, 256>>>(Wmix);
    k_mixout<<<NN / NPB, 256>>>(Wm1, bm1, Wm2, bm2, out_q, out_mu);
}

// round 15
// speedup vs baseline: 1.1640x; 1.1640x over previous
#include <cuda_runtime.h>
#include <cstdint>

#define NN 20000
#define EE 320000
#define CC 128
#define BB 20
#define RCUT_F 5.0f
#define EPS_F 1e-8f

// ---------------- scratch (device globals; no allocation allowed) ----------------
__device__ float g_x  [NN * 3 * CC];   // per-node context net output [N,3C]
__device__ float g_q1 [NN * CC];       // q + dq (accumulated)
__device__ float g_mu1[NN * 3 * CC];   // mu + dmu (accumulated)
__device__ float g_muV[NN * 3 * CC];
__device__ float g_muW[NN * 3 * CC];
// CSR (sender-major) for edge traversal with j-run gather reuse
__device__ int g_cnt[NN];
__device__ int g_off[NN + 1];
__device__ int g_cur[NN];
__device__ int g_perm[EE];

// ---------------- helpers ----------------
__device__ __forceinline__ void red4(float* p, float4 v) {
    asm volatile("red.global.add.v4.f32 [%0], {%1,%2,%3,%4};"
                 :: "l"(p), "f"(v.x), "f"(v.y), "f"(v.z), "f"(v.w) : "memory");
}
__device__ __forceinline__ float siluf(float x) {
    return x * (1.0f / (1.0f + __expf(-x)));
}
// packed fp32x2 FMA (Blackwell FFMA2): d = a*b + d
__device__ __forceinline__ void fma2(uint64_t& d, uint64_t a, uint64_t b) {
    asm("fma.rn.f32x2 %0, %1, %2, %0;" : "+l"(d) : "l"(a), "l"(b));
}
__device__ __forceinline__ uint64_t pk(float lo, float hi) {
    uint64_t r; asm("mov.b64 %0, {%1, %2};" : "=l"(r) : "f"(lo), "f"(hi)); return r;
}
__device__ __forceinline__ uint64_t bcast2(float w) {
    uint64_t r; asm("mov.b64 %0, {%1, %1};" : "=l"(r) : "f"(w)); return r;
}
__device__ __forceinline__ float2 unpk(uint64_t p) {
    float2 r; asm("mov.b64 {%0, %1}, %2;" : "=f"(r.x), "=f"(r.y) : "l"(p)); return r;
}
// cp.async (LDGSTS): zero-register weight staging
__device__ __forceinline__ void cpa16(uint32_t dst, const float* src) {
    asm volatile("cp.async.cg.shared.global [%0], [%1], 16;" :: "r"(dst), "l"(src));
}
#define CP_COMMIT() asm volatile("cp.async.commit_group;" ::: "memory")
#define CP_WAIT0()  asm volatile("cp.async.wait_group 0;" ::: "memory")

// Node-GEMV tiling (proven R11 shape): 256 threads, 16 nodes/block.
#define NPB 16
#define NH  8
#define STR 20   // padded tile row stride in floats

// ============================================================================
// CSR build (sender-major): histogram -> scan -> permutation
// ============================================================================
__global__ void k_zero() {
    int t = blockIdx.x * blockDim.x + threadIdx.x;
    if (t < NN) g_cnt[t] = 0;
}
__global__ void k_hist(const int* __restrict__ eidx) {
    int e = blockIdx.x * blockDim.x + threadIdx.x;
    if (e < EE) atomicAdd(&g_cnt[eidx[EE + e]], 1);   // key on SENDER j
}
#define SCAN_T 1024
#define SCAN_R 20   // 1024*20 = 20480 >= NN
__global__ __launch_bounds__(SCAN_T) void k_scan() {
    __shared__ int part[SCAN_T];
    const int t = threadIdx.x;
    int local[SCAN_R];
    int s = 0;
    #pragma unroll
    for (int r = 0; r < SCAN_R; r++) {
        int idx = t * SCAN_R + r;
        int c = (idx < NN) ? g_cnt[idx] : 0;
        local[r] = s;
        s += c;
    }
    part[t] = s;
    __syncthreads();
    for (int off = 1; off < SCAN_T; off <<= 1) {
        int v = (t >= off) ? part[t - off] : 0;
        __syncthreads();
        part[t] += v;
        __syncthreads();
    }
    const int excl = part[t] - s;
    #pragma unroll
    for (int r = 0; r < SCAN_R; r++) {
        int idx = t * SCAN_R + r;
        if (idx < NN) {
            int o = excl + local[r];
            g_off[idx] = o;
            g_cur[idx] = o;
        }
    }
    if (t == SCAN_T - 1) g_off[NN] = part[SCAN_T - 1];
}
__global__ void k_perm(const int* __restrict__ eidx) {
    int e = blockIdx.x * blockDim.x + threadIdx.x;
    if (e < EE) {
        int pos = atomicAdd(&g_cur[eidx[EE + e]], 1);  // SENDER j
        g_perm[pos] = e;
    }
}

// ============================================================================
// K1: context net  x = silu(q@W1+b1)@W2+b2 ; seed g_q1=q, g_mu1=mu  (R11)
// ============================================================================
#define K1R1 16
#define K1T1 (CC / K1R1)
#define K1R2 8
#define K1T2 (CC / K1R2)

__global__ __launch_bounds__(256) void k_context(
    const float* __restrict__ q, const float* __restrict__ mu,
    const float* __restrict__ W1, const float* __restrict__ b1,
    const float* __restrict__ W2, const float* __restrict__ b2)
{
    __shared__ __align__(16) float sqT[CC * STR];
    __shared__ __align__(16) float shT[CC * STR];
    __shared__ __align__(16) float sW[2][3 * CC * K1R2];
    const int tid  = threadIdx.x;
    const int d    = tid & 127;
    const int h    = tid >> 7;
    const int base = blockIdx.x * NPB;
    const uint32_t swb0 = (uint32_t)__cvta_generic_to_shared(sW[0]);
    const uint32_t swb1 = (uint32_t)__cvta_generic_to_shared(sW[1]);

    #pragma unroll
    for (int n2 = 0; n2 < NH; n2++) {
        const int n = n2 * 2 + h;
        float v = q[(base + n) * CC + d];
        sqT[d * STR + n] = v;
        g_q1[(base + n) * CC + d] = v;
    }
    {
        const float4* src = reinterpret_cast<const float4*>(&mu[base * 3 * CC]);
        float4* dst = reinterpret_cast<float4*>(&g_mu1[base * 3 * CC]);
        #pragma unroll
        for (int t = tid; t < NPB * 3 * CC / 4; t += 256) dst[t] = src[t];
    }
    __syncthreads();

    uint64_t acc[4];
    {
        float bb = b1[d];
        uint64_t bi = pk(bb, bb);
        #pragma unroll
        for (int m = 0; m < 4; m++) acc[m] = bi;

        #pragma unroll
        for (int t = tid; t < K1R1 * CC / 4; t += 256)
            cpa16(swb0 + t * 16, W1 + t * 4);
        CP_COMMIT();

        for (int kt = 0; kt < K1T1; kt++) {
            CP_WAIT0();
            __syncthreads();
            if (kt + 1 < K1T1) {
                const float* src = W1 + (kt + 1) * K1R1 * CC;
                uint32_t dstb = ((kt + 1) & 1) ? swb1 : swb0;
                #pragma unroll
                for (int t = tid; t < K1R1 * CC / 4; t += 256)
                    cpa16(dstb + t * 16, src + t * 4);
                CP_COMMIT();
            }
            const float* sWt = sW[kt & 1];
            #pragma unroll
            for (int r = 0; r < K1R1; r++) {
                const int k = kt * K1R1 + r;
                uint64_t ww = bcast2(sWt[r * CC + d]);
                const ulonglong2* row = reinterpret_cast<const ulonglong2*>(&sqT[k * STR + h * NH]);
                ulonglong2 v0 = row[0], v1 = row[1];
                fma2(acc[0], v0.x, ww); fma2(acc[1], v0.y, ww);
                fma2(acc[2], v1.x, ww); fma2(acc[3], v1.y, ww);
            }
        }
    }
    __syncthreads();
    #pragma unroll
    for (int m = 0; m < 4; m++) {
        float2 p = unpk(acc[m]);
        shT[d * STR + h * NH + 2*m]     = siluf(p.x);
        shT[d * STR + h * NH + 2*m + 1] = siluf(p.y);
    }
    __syncthreads();

    {
        uint64_t a2[3][4];
        #pragma unroll
        for (int g = 0; g < 3; g++) {
            float bb = b2[g * CC + d];
            uint64_t bi = pk(bb, bb);
            #pragma unroll
            for (int m = 0; m < 4; m++) a2[g][m] = bi;
        }
        #pragma unroll
        for (int t = tid; t < K1R2 * 3 * CC / 4; t += 256)
            cpa16(swb0 + t * 16, W2 + t * 4);
        CP_COMMIT();

        for (int kt = 0; kt < K1T2; kt++) {
            CP_WAIT0();
            __syncthreads();
            if (kt + 1 < K1T2) {
                const float* src = W2 + (kt + 1) * K1R2 * 3 * CC;
                uint32_t dstb = ((kt + 1) & 1) ? swb1 : swb0;
                #pragma unroll
                for (int t = tid; t < K1R2 * 3 * CC / 4; t += 256)
                    cpa16(dstb + t * 16, src + t * 4);
                CP_COMMIT();
            }
            const float* sWt = sW[kt & 1];
            #pragma unroll
            for (int r = 0; r < K1R2; r++) {
                const int k = kt * K1R2 + r;
                uint64_t w0 = bcast2(sWt[r * 3 * CC + 0 * CC + d]);
                uint64_t w1 = bcast2(sWt[r * 3 * CC + 1 * CC + d]);
                uint64_t w2 = bcast2(sWt[r * 3 * CC + 2 * CC + d]);
                const ulonglong2* row = reinterpret_cast<const ulonglong2*>(&shT[k * STR + h * NH]);
                ulonglong2 v0 = row[0], v1 = row[1];
                fma2(a2[0][0], v0.x, w0); fma2(a2[0][1], v0.y, w0);
                fma2(a2[0][2], v1.x, w0); fma2(a2[0][3], v1.y, w0);
                fma2(a2[1][0], v0.x, w1); fma2(a2[1][1], v0.y, w1);
                fma2(a2[1][2], v1.x, w1); fma2(a2[1][3], v1.y, w1);
                fma2(a2[2][0], v0.x, w2); fma2(a2[2][1], v0.y, w2);
                fma2(a2[2][2], v1.x, w2); fma2(a2[2][3], v1.y, w2);
            }
        }
        #pragma unroll
        for (int g = 0; g < 3; g++) {
            #pragma unroll
            for (int m = 0; m < 4; m++) {
                float2 p = unpk(a2[g][m]);
                g_x[(base + h * NH + 2*m)     * 3 * CC + g * CC + d] = p.x;
                g_x[(base + h * NH + 2*m + 1) * 3 * CC + g * CC + d] = p.y;
            }
        }
    }
}

// ============================================================================
// K2: edge kernel, R11 scatter form + sender-sorted traversal.
// One warp per 4 CSR slots; filter GEMV keeps 4-edge ILP; x[j]/mu[j] reloaded
// only when j changes between consecutive edges (warp-uniform branch).
// ============================================================================
#define EPW 4
#define EWARPS 8

__global__ __launch_bounds__(256) void k_edge(
    const int*   __restrict__ eidx,     // [2,E]
    const float* __restrict__ ew,       // [E]
    const float* __restrict__ evs,      // [E,3]
    const float* __restrict__ attrs,    // [E,B]
    const float* __restrict__ Wf,       // [B,3C]
    const float* __restrict__ bf,       // [3C]
    const float* __restrict__ mu)       // [N,3,C]
{
    __shared__ __align__(16) float sWf[BB * 3 * CC];
    __shared__ __align__(16) float sbf[3 * CC];

    for (int t = threadIdx.x; t < BB * 3 * CC / 4; t += 256)
        reinterpret_cast<float4*>(sWf)[t] = reinterpret_cast<const float4*>(Wf)[t];
    for (int t = threadIdx.x; t < 3 * CC / 4; t += 256)
        reinterpret_cast<float4*>(sbf)[t] = reinterpret_cast<const float4*>(bf)[t];
    __syncthreads();

    const int lane  = threadIdx.x & 31;
    const int wid   = threadIdx.x >> 5;
    const int c0    = lane * 4;
    const int nwarp = gridDim.x * EWARPS;

    const float4 bq = *reinterpret_cast<const float4*>(&sbf[c0]);
    const float4 bR = *reinterpret_cast<const float4*>(&sbf[CC + c0]);
    const float4 bm = *reinterpret_cast<const float4*>(&sbf[2 * CC + c0]);

    for (int gidx = blockIdx.x * EWARPS + wid; gidx < EE / EPW; gidx += nwarp) {
        const int k0 = gidx * EPW;
        int ee[EPW], ii[EPW], jj[EPW];
        float fc[EPW], av[EPW];
        #pragma unroll
        for (int t = 0; t < EPW; t++) {
            const int e = g_perm[k0 + t];
            ee[t] = e;
            ii[t] = eidx[e];
            jj[t] = eidx[EE + e];
            float w = ew[e];
            fc[t] = (w < RCUT_F)
                ? 0.5f * (__cosf((3.14159265358979f / RCUT_F) * w) + 1.0f) : 0.0f;
            av[t] = (lane < BB) ? attrs[e * BB + lane] : 0.0f;
        }

        uint64_t acc[EPW][6];
        #pragma unroll
        for (int t = 0; t < EPW; t++) {
            acc[t][0] = pk(bq.x, bq.y); acc[t][1] = pk(bq.z, bq.w);
            acc[t][2] = pk(bR.x, bR.y); acc[t][3] = pk(bR.z, bR.w);
            acc[t][4] = pk(bm.x, bm.y); acc[t][5] = pk(bm.z, bm.w);
        }

        #pragma unroll
        for (int b = 0; b < BB; b++) {
            ulonglong2 f0 = *reinterpret_cast<const ulonglong2*>(&sWf[b * 3 * CC + c0]);
            ulonglong2 f1 = *reinterpret_cast<const ulonglong2*>(&sWf[b * 3 * CC + CC + c0]);
            ulonglong2 f2 = *reinterpret_cast<const ulonglong2*>(&sWf[b * 3 * CC + 2 * CC + c0]);
            #pragma unroll
            for (int t = 0; t < EPW; t++) {
                uint64_t aw = bcast2(__shfl_sync(0xFFFFFFFFu, av[t], b));
                fma2(acc[t][0], f0.x, aw); fma2(acc[t][1], f0.y, aw);
                fma2(acc[t][2], f1.x, aw); fma2(acc[t][3], f1.y, aw);
                fma2(acc[t][4], f2.x, aw); fma2(acc[t][5], f2.y, aw);
            }
        }

        float4 x0, x1, x2, mj0, mj1, mj2;
        #pragma unroll
        for (int t = 0; t < EPW; t++) {
            const int e = ee[t];
            const float f = fc[t];
            const float ev0 = evs[e * 3 + 0];
            const float ev1 = evs[e * 3 + 1];
            const float ev2 = evs[e * 3 + 2];

            // reload gathers only when sender changes (warp-uniform branch)
            if (t == 0 || jj[t] != jj[t - 1]) {
                const float4* xb  = reinterpret_cast<const float4*>(&g_x[jj[t] * 3 * CC]);
                const float4* mub = reinterpret_cast<const float4*>(&mu[jj[t] * 3 * CC]);
                x0  = xb[lane];
                x1  = xb[32 + lane];
                x2  = xb[64 + lane];
                mj0 = mub[lane];
                mj1 = mub[32 + lane];
                mj2 = mub[64 + lane];
            }

            float2 wq0 = unpk(acc[t][0]), wq1 = unpk(acc[t][1]);
            float2 wR0 = unpk(acc[t][2]), wR1 = unpk(acc[t][3]);
            float2 wm0 = unpk(acc[t][4]), wm1 = unpk(acc[t][5]);

            float4 dq = make_float4(x0.x * wq0.x * f, x0.y * wq0.y * f,
                                    x0.z * wq1.x * f, x0.w * wq1.y * f);
            red4(&g_q1[ii[t] * CC + c0], dq);

            float4 cR = make_float4(x1.x * wR0.x * f, x1.y * wR0.y * f,
                                    x1.z * wR1.x * f, x1.w * wR1.y * f);
            float4 cm = make_float4(x2.x * wm0.x * f, x2.y * wm0.y * f,
                                    x2.z * wm1.x * f, x2.w * wm1.y * f);

            float4 dm0 = make_float4(fmaf(cm.x, mj0.x, cR.x * ev0),
                                     fmaf(cm.y, mj0.y, cR.y * ev0),
                                     fmaf(cm.z, mj0.z, cR.z * ev0),
                                     fmaf(cm.w, mj0.w, cR.w * ev0));
            red4(&g_mu1[(ii[t] * 3 + 0) * CC + c0], dm0);
            float4 dm1 = make_float4(fmaf(cm.x, mj1.x, cR.x * ev1),
                                     fmaf(cm.y, mj1.y, cR.y * ev1),
                                     fmaf(cm.z, mj1.z, cR.z * ev1),
                                     fmaf(cm.w, mj1.w, cR.w * ev1));
            red4(&g_mu1[(ii[t] * 3 + 1) * CC + c0], dm1);
            float4 dm2 = make_float4(fmaf(cm.x, mj2.x, cR.x * ev2),
                                     fmaf(cm.y, mj2.y, cR.y * ev2),
                                     fmaf(cm.z, mj2.z, cR.z * ev2),
                                     fmaf(cm.w, mj2.w, cR.w * ev2));
            red4(&g_mu1[(ii[t] * 3 + 2) * CC + c0], dm2);
        }
    }
}

// ============================================================================
// K3a: mu_mix = mu1 @ W_mix -> muV, muW.  (R11 shape)
// ============================================================================
#define K3R 8
#define K3T (CC / K3R)

__global__ __launch_bounds__(256) void k_mumix(const float* __restrict__ Wmix)
{
    __shared__ __align__(16) float sT[CC * STR];
    __shared__ __align__(16) float sW[2][K3R * 2 * CC];
    const int tid  = threadIdx.x;
    const int d    = tid & 127;
    const int h    = tid >> 7;
    const int base = blockIdx.x * NPB;
    const uint32_t swb0 = (uint32_t)__cvta_generic_to_shared(sW[0]);
    const uint32_t swb1 = (uint32_t)__cvta_generic_to_shared(sW[1]);

    #pragma unroll
    for (int n2 = 0; n2 < NH; n2++) {
        const int r = n2 * 2 + h;
        sT[d * STR + r] = g_mu1[(base + r) * CC + d];
    }
    __syncthreads();

    uint64_t acc[2][4];
    #pragma unroll
    for (int g = 0; g < 2; g++)
        #pragma unroll
        for (int m = 0; m < 4; m++) acc[g][m] = 0ull;

    #pragma unroll
    for (int t = tid; t < K3R * 2 * CC / 4; t += 256)
        cpa16(swb0 + t * 16, Wmix + t * 4);
    CP_COMMIT();

    for (int kt = 0; kt < K3T; kt++) {
        CP_WAIT0();
        __syncthreads();
        if (kt + 1 < K3T) {
            const float* src = Wmix + (kt + 1) * K3R * 2 * CC;
            uint32_t dstb = ((kt + 1) & 1) ? swb1 : swb0;
            #pragma unroll
            for (int t = tid; t < K3R * 2 * CC / 4; t += 256)
                cpa16(dstb + t * 16, src + t * 4);
            CP_COMMIT();
        }
        const float* sWt = sW[kt & 1];
        #pragma unroll
        for (int r = 0; r < K3R; r++) {
            const int k = kt * K3R + r;
            uint64_t w0 = bcast2(sWt[r * 2 * CC + 0 * CC + d]);
            uint64_t w1 = bcast2(sWt[r * 2 * CC + 1 * CC + d]);
            const ulonglong2* row = reinterpret_cast<const ulonglong2*>(&sT[k * STR + h * NH]);
            ulonglong2 v0 = row[0], v1 = row[1];
            fma2(acc[0][0], v0.x, w0); fma2(acc[0][1], v0.y, w0);
            fma2(acc[0][2], v1.x, w0); fma2(acc[0][3], v1.y, w0);
            fma2(acc[1][0], v0.x, w1); fma2(acc[1][1], v0.y, w1);
            fma2(acc[1][2], v1.x, w1); fma2(acc[1][3], v1.y, w1);
        }
    }
    #pragma unroll
    for (int g = 0; g < 2; g++) {
        float* dst = (g == 0) ? g_muV : g_muW;
        #pragma unroll
        for (int m = 0; m < 4; m++) {
            float2 p = unpk(acc[g][m]);
            dst[(base + h * NH + 2*m)     * CC + d] = p.x;
            dst[(base + h * NH + 2*m + 1) * CC + d] = p.y;
        }
    }
}

// ============================================================================
// K3b: mixing MLP + final outputs.  (R11 shape)
// ============================================================================
#define K4R1 16
#define K4T1 (2 * CC / K4R1)
#define K4R2 8
#define K4T2 (CC / K4R2)

__global__ __launch_bounds__(256) void k_mixout(
    const float* __restrict__ Wm1, const float* __restrict__ bm1,
    const float* __restrict__ Wm2, const float* __restrict__ bm2,
    float* __restrict__ out_q, float* __restrict__ out_mu)
{
    __shared__ __align__(16) float buf[2 * CC * STR];
    __shared__ __align__(16) float sscal[NPB * CC];
    __shared__ __align__(16) float sW[2][3 * CC * K4R2];
    const int tid  = threadIdx.x;
    const int d    = tid & 127;
    const int h    = tid >> 7;
    const int base = blockIdx.x * NPB;
    const uint32_t swb0 = (uint32_t)__cvta_generic_to_shared(sW[0]);
    const uint32_t swb1 = (uint32_t)__cvta_generic_to_shared(sW[1]);

    #pragma unroll
    for (int n2 = 0; n2 < NH; n2++) {
        const int n = n2 * 2 + h;
        const int node = base + n;
        float q1v = g_q1[node * CC + d];
        float v0 = g_muV[(node * 3 + 0) * CC + d];
        float v1 = g_muV[(node * 3 + 1) * CC + d];
        float v2 = g_muV[(node * 3 + 2) * CC + d];
        float w0 = g_muW[(node * 3 + 0) * CC + d];
        float w1 = g_muW[(node * 3 + 1) * CC + d];
        float w2 = g_muW[(node * 3 + 2) * CC + d];
        float vn = sqrtf(fmaf(v0, v0, fmaf(v1, v1, fmaf(v2, v2, EPS_F))));
        sscal[n * CC + d] = fmaf(v0, w0, fmaf(v1, w1, v2 * w2));
        buf[d * STR + n] = q1v;
        buf[(CC + d) * STR + n] = vn;
    }
    __syncthreads();

    uint64_t acc[4];
    {
        float bb = bm1[d];
        uint64_t bi = pk(bb, bb);
        #pragma unroll
        for (int m = 0; m < 4; m++) acc[m] = bi;

        #pragma unroll
        for (int t = tid; t < K4R1 * CC / 4; t += 256)
            cpa16(swb0 + t * 16, Wm1 + t * 4);
        CP_COMMIT();

        for (int kt = 0; kt < K4T1; kt++) {
            CP_WAIT0();
            __syncthreads();
            if (kt + 1 < K4T1) {
                const float* src = Wm1 + (kt + 1) * K4R1 * CC;
                uint32_t dstb = ((kt + 1) & 1) ? swb1 : swb0;
                #pragma unroll
                for (int t = tid; t < K4R1 * CC / 4; t += 256)
                    cpa16(dstb + t * 16, src + t * 4);
                CP_COMMIT();
            }
            const float* sWt = sW[kt & 1];
            #pragma unroll
            for (int r = 0; r < K4R1; r++) {
                const int k = kt * K4R1 + r;
                uint64_t ww = bcast2(sWt[r * CC + d]);
                const ulonglong2* row = reinterpret_cast<const ulonglong2*>(&buf[k * STR + h * NH]);
                ulonglong2 v0 = row[0], v1 = row[1];
                fma2(acc[0], v0.x, ww); fma2(acc[1], v0.y, ww);
                fma2(acc[2], v1.x, ww); fma2(acc[3], v1.y, ww);
            }
        }
    }
    __syncthreads();
    #pragma unroll
    for (int m = 0; m < 4; m++) {
        float2 p = unpk(acc[m]);
        buf[(CC + d) * STR + h * NH + 2*m]     = siluf(p.x);
        buf[(CC + d) * STR + h * NH + 2*m + 1] = siluf(p.y);
    }
    __syncthreads();

    uint64_t a[3][4];
    #pragma unroll
    for (int g = 0; g < 3; g++) {
        float bb = bm2[g * CC + d];
        uint64_t bi = pk(bb, bb);
        #pragma unroll
        for (int m = 0; m < 4; m++) a[g][m] = bi;
    }
    #pragma unroll
    for (int t = tid; t < K4R2 * 3 * CC / 4; t += 256)
        cpa16(swb0 + t * 16, Wm2 + t * 4);
    CP_COMMIT();

    for (int kt = 0; kt < K4T2; kt++) {
        CP_WAIT0();
        __syncthreads();
        if (kt + 1 < K4T2) {
            const float* src = Wm2 + (kt + 1) * K4R2 * 3 * CC;
            uint32_t dstb = ((kt + 1) & 1) ? swb1 : swb0;
            #pragma unroll
            for (int t = tid; t < K4R2 * 3 * CC / 4; t += 256)
                cpa16(dstb + t * 16, src + t * 4);
            CP_COMMIT();
        }
        const float* sWt = sW[kt & 1];
        #pragma unroll
        for (int r = 0; r < K4R2; r++) {
            const int k = kt * K4R2 + r;
            uint64_t w0 = bcast2(sWt[r * 3 * CC + 0 * CC + d]);
            uint64_t w1 = bcast2(sWt[r * 3 * CC + 1 * CC + d]);
            uint64_t w2 = bcast2(sWt[r * 3 * CC + 2 * CC + d]);
            const ulonglong2* row = reinterpret_cast<const ulonglong2*>(&buf[(CC + k) * STR + h * NH]);
            ulonglong2 v0 = row[0], v1 = row[1];
            fma2(a[0][0], v0.x, w0); fma2(a[0][1], v0.y, w0);
            fma2(a[0][2], v1.x, w0); fma2(a[0][3], v1.y, w0);
            fma2(a[1][0], v0.x, w1); fma2(a[1][1], v0.y, w1);
            fma2(a[1][2], v1.x, w1); fma2(a[1][3], v1.y, w1);
            fma2(a[2][0], v0.x, w2); fma2(a[2][1], v0.y, w2);
            fma2(a[2][2], v1.x, w2); fma2(a[2][3], v1.y, w2);
        }
    }

    #pragma unroll
    for (int m = 0; m < 4; m++) {
        float2 p0 = unpk(a[0][m]);
        float2 p1 = unpk(a[1][m]);
        float2 p2 = unpk(a[2][m]);
        #pragma unroll
        for (int t = 0; t < 2; t++) {
            const int n = h * NH + 2*m + t;
            const int node = base + n;
            float y0 = t ? p0.y : p0.x;
            float y1 = t ? p1.y : p1.x;
            float y2 = t ? p2.y : p2.x;
            float q1v  = buf[d * STR + n];
            float scal = sscal[n * CC + d];
            out_q[node * CC + d] = q1v + y0 + y2 * scal;
            #pragma unroll
            for (int v = 0; v < 3; v++) {
                float mw = g_muW[(node * 3 + v) * CC + d];
                float m1 = g_mu1[(node * 3 + v) * CC + d];
                out_mu[(node * 3 + v) * CC + d] = fmaf(y1, mw, m1);
            }
        }
    }
}

// ============================================================================
extern "C" void kernel_launch(void* const* d_in, const int* in_sizes, int n_in,
                              void* d_out, int out_size)
{
    const float* q     = (const float*)d_in[0];
    const float* mu    = (const float*)d_in[1];
    const int*   eidx  = (const int*)  d_in[2];
    const float* ew    = (const float*)d_in[3];
    const float* evs   = (const float*)d_in[4];
    const float* attrs = (const float*)d_in[5];
    const float* Wf    = (const float*)d_in[6];
    const float* bf    = (const float*)d_in[7];
    const float* W1    = (const float*)d_in[8];
    const float* b1    = (const float*)d_in[9];
    const float* W2    = (const float*)d_in[10];
    const float* b2    = (const float*)d_in[11];
    const float* Wmix  = (const float*)d_in[12];
    const float* Wm1   = (const float*)d_in[13];
    const float* bm1   = (const float*)d_in[14];
    const float* Wm2   = (const float*)d_in[15];
    const float* bm2   = (const float*)d_in[16];

    float* out_q  = (float*)d_out;
    float* out_mu = out_q + (size_t)NN * CC;

    // CSR build (sender-major edge ordering) — overlaps nothing, ~20 us
    k_zero<<<(NN + 255) / 256, 256>>>();
    k_hist<<<(EE + 255) / 256, 256>>>(eidx);
    k_scan<<<1, SCAN_T>>>();
    k_perm<<<(EE + 255) / 256, 256>>>(eidx);

    k_context<<<NN / NPB, 256>>>(q, mu, W1, b1, W2, b2);
    k_edge<<<1184, 256>>>(eidx, ew, evs, attrs, Wf, bf, mu);
    k_mumix<<<(3 * NN) / NPB, 256>>>(Wmix);
    k_mixout<<<NN / NPB, 256>>>(Wm1, bm1, Wm2, bm2, out_q, out_mu);
}

// round 16
// speedup vs baseline: 1.4448x; 1.2413x over previous
#include <cuda_runtime.h>
#include <cstdint>

#define NN 20000
#define EE 320000
#define CC 128
#define BB 20
#define RCUT_F 5.0f
#define EPS_F 1e-8f

// ---------------- scratch (device globals; no allocation allowed) ----------------
__device__ float g_x  [NN * 3 * CC];   // per-node context net output [N,3C]
__device__ float g_q1 [NN * CC];       // q + dq (accumulated)
__device__ float g_mu1[NN * 3 * CC];   // mu + dmu (accumulated)
__device__ float g_muV[NN * 3 * CC];
__device__ float g_muW[NN * 3 * CC];

// ---------------- helpers ----------------
__device__ __forceinline__ void red4(float* p, float4 v) {
    asm volatile("red.global.add.v4.f32 [%0], {%1,%2,%3,%4};"
                 :: "l"(p), "f"(v.x), "f"(v.y), "f"(v.z), "f"(v.w) : "memory");
}
__device__ __forceinline__ float siluf(float x) {
    return x * (1.0f / (1.0f + __expf(-x)));
}
// packed fp32x2 FMA (Blackwell FFMA2): d = a*b + d
__device__ __forceinline__ void fma2(uint64_t& d, uint64_t a, uint64_t b) {
    asm("fma.rn.f32x2 %0, %1, %2, %0;" : "+l"(d) : "l"(a), "l"(b));
}
__device__ __forceinline__ uint64_t pk(float lo, float hi) {
    uint64_t r; asm("mov.b64 %0, {%1, %2};" : "=l"(r) : "f"(lo), "f"(hi)); return r;
}
__device__ __forceinline__ uint64_t bcast2(float w) {
    uint64_t r; asm("mov.b64 %0, {%1, %1};" : "=l"(r) : "f"(w)); return r;
}
__device__ __forceinline__ float2 unpk(uint64_t p) {
    float2 r; asm("mov.b64 {%0, %1}, %2;" : "=f"(r.x), "=f"(r.y) : "l"(p)); return r;
}
// cp.async (LDGSTS): zero-register weight staging
__device__ __forceinline__ void cpa16(uint32_t dst, const float* src) {
    asm volatile("cp.async.cg.shared.global [%0], [%1], 16;" :: "r"(dst), "l"(src));
}
#define CP_COMMIT() asm volatile("cp.async.commit_group;" ::: "memory")
#define CP_WAIT0()  asm volatile("cp.async.wait_group 0;" ::: "memory")

// PDL: allow this kernel's successor to launch early; it must gridDepSync
// before touching anything we write.
#define PDL_TRIGGER() cudaTriggerProgrammaticLaunchCompletion()
#define PDL_WAIT()    cudaGridDependencySynchronize()

// Node-GEMV tiling (proven R11 shape): 256 threads, 16 nodes/block.
#define NPB 16
#define NH  8
#define STR 20   // padded tile row stride in floats

// ============================================================================
// K1: context net  x = silu(q@W1+b1)@W2+b2 ; seed g_q1=q, g_mu1=mu
// PDL preamble: stage W1 tile 0 (input-only) before syncing on predecessor
// (the previous graph iteration's k_mixout, which READS g_q1/g_mu1).
// ============================================================================
#define K1R1 16
#define K1T1 (CC / K1R1)
#define K1R2 8
#define K1T2 (CC / K1R2)

__global__ __launch_bounds__(256) void k_context(
    const float* __restrict__ q, const float* __restrict__ mu,
    const float* __restrict__ W1, const float* __restrict__ b1,
    const float* __restrict__ W2, const float* __restrict__ b2)
{
    __shared__ __align__(16) float sqT[CC * STR];
    __shared__ __align__(16) float shT[CC * STR];
    __shared__ __align__(16) float sW[2][3 * CC * K1R2];
    const int tid  = threadIdx.x;
    const int d    = tid & 127;
    const int h    = tid >> 7;
    const int base = blockIdx.x * NPB;
    const uint32_t swb0 = (uint32_t)__cvta_generic_to_shared(sW[0]);
    const uint32_t swb1 = (uint32_t)__cvta_generic_to_shared(sW[1]);

    PDL_TRIGGER();
    // preamble: stage W1 tile 0 (reads only kernel inputs)
    #pragma unroll
    for (int t = tid; t < K1R1 * CC / 4; t += 256)
        cpa16(swb0 + t * 16, W1 + t * 4);
    CP_COMMIT();
    PDL_WAIT();   // predecessor (prev-iter k_mixout) fully done: safe to write g_q1/g_mu1

    #pragma unroll
    for (int n2 = 0; n2 < NH; n2++) {
        const int n = n2 * 2 + h;
        float v = q[(base + n) * CC + d];
        sqT[d * STR + n] = v;
        g_q1[(base + n) * CC + d] = v;
    }
    {
        const float4* src = reinterpret_cast<const float4*>(&mu[base * 3 * CC]);
        float4* dst = reinterpret_cast<float4*>(&g_mu1[base * 3 * CC]);
        #pragma unroll
        for (int t = tid; t < NPB * 3 * CC / 4; t += 256) dst[t] = src[t];
    }
    __syncthreads();

    // ---- layer 1: h = silu(q @ W1 + b1) ----
    uint64_t acc[4];
    {
        float bb = b1[d];
        uint64_t bi = pk(bb, bb);
        #pragma unroll
        for (int m = 0; m < 4; m++) acc[m] = bi;

        for (int kt = 0; kt < K1T1; kt++) {
            CP_WAIT0();
            __syncthreads();
            if (kt + 1 < K1T1) {
                const float* src = W1 + (kt + 1) * K1R1 * CC;
                uint32_t dstb = ((kt + 1) & 1) ? swb1 : swb0;
                #pragma unroll
                for (int t = tid; t < K1R1 * CC / 4; t += 256)
                    cpa16(dstb + t * 16, src + t * 4);
                CP_COMMIT();
            }
            const float* sWt = sW[kt & 1];
            #pragma unroll
            for (int r = 0; r < K1R1; r++) {
                const int k = kt * K1R1 + r;
                uint64_t ww = bcast2(sWt[r * CC + d]);
                const ulonglong2* row = reinterpret_cast<const ulonglong2*>(&sqT[k * STR + h * NH]);
                ulonglong2 v0 = row[0], v1 = row[1];
                fma2(acc[0], v0.x, ww); fma2(acc[1], v0.y, ww);
                fma2(acc[2], v1.x, ww); fma2(acc[3], v1.y, ww);
            }
        }
    }
    __syncthreads();
    #pragma unroll
    for (int m = 0; m < 4; m++) {
        float2 p = unpk(acc[m]);
        shT[d * STR + h * NH + 2*m]     = siluf(p.x);
        shT[d * STR + h * NH + 2*m + 1] = siluf(p.y);
    }
    __syncthreads();

    // ---- layer 2: x = h @ W2 + b2, 3 groups fused ----
    {
        uint64_t a2[3][4];
        #pragma unroll
        for (int g = 0; g < 3; g++) {
            float bb = b2[g * CC + d];
            uint64_t bi = pk(bb, bb);
            #pragma unroll
            for (int m = 0; m < 4; m++) a2[g][m] = bi;
        }
        #pragma unroll
        for (int t = tid; t < K1R2 * 3 * CC / 4; t += 256)
            cpa16(swb0 + t * 16, W2 + t * 4);
        CP_COMMIT();

        for (int kt = 0; kt < K1T2; kt++) {
            CP_WAIT0();
            __syncthreads();
            if (kt + 1 < K1T2) {
                const float* src = W2 + (kt + 1) * K1R2 * 3 * CC;
                uint32_t dstb = ((kt + 1) & 1) ? swb1 : swb0;
                #pragma unroll
                for (int t = tid; t < K1R2 * 3 * CC / 4; t += 256)
                    cpa16(dstb + t * 16, src + t * 4);
                CP_COMMIT();
            }
            const float* sWt = sW[kt & 1];
            #pragma unroll
            for (int r = 0; r < K1R2; r++) {
                const int k = kt * K1R2 + r;
                uint64_t w0 = bcast2(sWt[r * 3 * CC + 0 * CC + d]);
                uint64_t w1 = bcast2(sWt[r * 3 * CC + 1 * CC + d]);
                uint64_t w2 = bcast2(sWt[r * 3 * CC + 2 * CC + d]);
                const ulonglong2* row = reinterpret_cast<const ulonglong2*>(&shT[k * STR + h * NH]);
                ulonglong2 v0 = row[0], v1 = row[1];
                fma2(a2[0][0], v0.x, w0); fma2(a2[0][1], v0.y, w0);
                fma2(a2[0][2], v1.x, w0); fma2(a2[0][3], v1.y, w0);
                fma2(a2[1][0], v0.x, w1); fma2(a2[1][1], v0.y, w1);
                fma2(a2[1][2], v1.x, w1); fma2(a2[1][3], v1.y, w1);
                fma2(a2[2][0], v0.x, w2); fma2(a2[2][1], v0.y, w2);
                fma2(a2[2][2], v1.x, w2); fma2(a2[2][3], v1.y, w2);
            }
        }
        #pragma unroll
        for (int g = 0; g < 3; g++) {
            #pragma unroll
            for (int m = 0; m < 4; m++) {
                float2 p = unpk(a2[g][m]);
                g_x[(base + h * NH + 2*m)     * 3 * CC + g * CC + d] = p.x;
                g_x[(base + h * NH + 2*m + 1) * 3 * CC + g * CC + d] = p.y;
            }
        }
    }
}

// ============================================================================
// K2: edge kernel (R11 proven form). One warp per 4 edges, natural order,
// Wf staged in smem, FFMA2 filter GEMV, L2 gathers, red.v4 scatters.
// PDL preamble: Wf/bf staging (input-only) overlaps k_context's tail.
// ============================================================================
#define EPW 4
#define EWARPS 8

__global__ __launch_bounds__(256) void k_edge(
    const int*   __restrict__ eidx,     // [2,E]
    const float* __restrict__ ew,       // [E]
    const float* __restrict__ evs,      // [E,3]
    const float* __restrict__ attrs,    // [E,B]
    const float* __restrict__ Wf,       // [B,3C]
    const float* __restrict__ bf,       // [3C]
    const float* __restrict__ mu)       // [N,3,C]
{
    __shared__ __align__(16) float sWf[BB * 3 * CC];
    __shared__ __align__(16) float sbf[3 * CC];

    PDL_TRIGGER();
    for (int t = threadIdx.x; t < BB * 3 * CC / 4; t += 256)
        reinterpret_cast<float4*>(sWf)[t] = reinterpret_cast<const float4*>(Wf)[t];
    for (int t = threadIdx.x; t < 3 * CC / 4; t += 256)
        reinterpret_cast<float4*>(sbf)[t] = reinterpret_cast<const float4*>(bf)[t];
    PDL_WAIT();   // k_context fully done: g_x/g_q1/g_mu1 valid
    __syncthreads();

    const int lane  = threadIdx.x & 31;
    const int wid   = threadIdx.x >> 5;
    const int c0    = lane * 4;
    const int nwarp = gridDim.x * EWARPS;

    const float4 bq = *reinterpret_cast<const float4*>(&sbf[c0]);
    const float4 bR = *reinterpret_cast<const float4*>(&sbf[CC + c0]);
    const float4 bm = *reinterpret_cast<const float4*>(&sbf[2 * CC + c0]);

    for (int gidx = blockIdx.x * EWARPS + wid; gidx < EE / EPW; gidx += nwarp) {
        const int e0 = gidx * EPW;
        int ii[EPW], jj[EPW];
        float fc[EPW], av[EPW];
        #pragma unroll
        for (int t = 0; t < EPW; t++) {
            ii[t] = eidx[e0 + t];
            jj[t] = eidx[EE + e0 + t];
            float w = ew[e0 + t];
            fc[t] = (w < RCUT_F)
                ? 0.5f * (__cosf((3.14159265358979f / RCUT_F) * w) + 1.0f) : 0.0f;
            av[t] = (lane < BB) ? attrs[(e0 + t) * BB + lane] : 0.0f;
        }

        uint64_t acc[EPW][6];
        #pragma unroll
        for (int t = 0; t < EPW; t++) {
            acc[t][0] = pk(bq.x, bq.y); acc[t][1] = pk(bq.z, bq.w);
            acc[t][2] = pk(bR.x, bR.y); acc[t][3] = pk(bR.z, bR.w);
            acc[t][4] = pk(bm.x, bm.y); acc[t][5] = pk(bm.z, bm.w);
        }

        #pragma unroll
        for (int b = 0; b < BB; b++) {
            ulonglong2 f0 = *reinterpret_cast<const ulonglong2*>(&sWf[b * 3 * CC + c0]);
            ulonglong2 f1 = *reinterpret_cast<const ulonglong2*>(&sWf[b * 3 * CC + CC + c0]);
            ulonglong2 f2 = *reinterpret_cast<const ulonglong2*>(&sWf[b * 3 * CC + 2 * CC + c0]);
            #pragma unroll
            for (int t = 0; t < EPW; t++) {
                uint64_t aw = bcast2(__shfl_sync(0xFFFFFFFFu, av[t], b));
                fma2(acc[t][0], f0.x, aw); fma2(acc[t][1], f0.y, aw);
                fma2(acc[t][2], f1.x, aw); fma2(acc[t][3], f1.y, aw);
                fma2(acc[t][4], f2.x, aw); fma2(acc[t][5], f2.y, aw);
            }
        }

        #pragma unroll
        for (int t = 0; t < EPW; t++) {
            const int e = e0 + t;
            const float f = fc[t];
            const float ev0 = evs[e * 3 + 0];
            const float ev1 = evs[e * 3 + 1];
            const float ev2 = evs[e * 3 + 2];

            float2 wq0 = unpk(acc[t][0]), wq1 = unpk(acc[t][1]);
            float2 wR0 = unpk(acc[t][2]), wR1 = unpk(acc[t][3]);
            float2 wm0 = unpk(acc[t][4]), wm1 = unpk(acc[t][5]);

            const float4* xb = reinterpret_cast<const float4*>(&g_x[jj[t] * 3 * CC]);
            float4 x0 = xb[lane];
            float4 x1 = xb[32 + lane];
            float4 x2 = xb[64 + lane];

            float4 dq = make_float4(x0.x * wq0.x * f, x0.y * wq0.y * f,
                                    x0.z * wq1.x * f, x0.w * wq1.y * f);
            red4(&g_q1[ii[t] * CC + c0], dq);

            float4 cR = make_float4(x1.x * wR0.x * f, x1.y * wR0.y * f,
                                    x1.z * wR1.x * f, x1.w * wR1.y * f);
            float4 cm = make_float4(x2.x * wm0.x * f, x2.y * wm0.y * f,
                                    x2.z * wm1.x * f, x2.w * wm1.y * f);

            const float4* mub = reinterpret_cast<const float4*>(&mu[jj[t] * 3 * CC]);
            #pragma unroll
            for (int v = 0; v < 3; v++) {
                float evv = (v == 0) ? ev0 : (v == 1) ? ev1 : ev2;
                float4 mj = mub[v * 32 + lane];
                float4 dm = make_float4(fmaf(cm.x, mj.x, cR.x * evv),
                                        fmaf(cm.y, mj.y, cR.y * evv),
                                        fmaf(cm.z, mj.z, cR.z * evv),
                                        fmaf(cm.w, mj.w, cR.w * evv));
                red4(&g_mu1[(ii[t] * 3 + v) * CC + c0], dm);
            }
        }
    }
}

// ============================================================================
// K3a: mu_mix = mu1 @ W_mix -> muV, muW. (R11 shape + PDL preamble)
// ============================================================================
#define K3R 8
#define K3T (CC / K3R)

__global__ __launch_bounds__(256) void k_mumix(const float* __restrict__ Wmix)
{
    __shared__ __align__(16) float sT[CC * STR];
    __shared__ __align__(16) float sW[2][K3R * 2 * CC];
    const int tid  = threadIdx.x;
    const int d    = tid & 127;
    const int h    = tid >> 7;
    const int base = blockIdx.x * NPB;
    const uint32_t swb0 = (uint32_t)__cvta_generic_to_shared(sW[0]);
    const uint32_t swb1 = (uint32_t)__cvta_generic_to_shared(sW[1]);

    PDL_TRIGGER();
    #pragma unroll
    for (int t = tid; t < K3R * 2 * CC / 4; t += 256)
        cpa16(swb0 + t * 16, Wmix + t * 4);
    CP_COMMIT();
    PDL_WAIT();   // k_edge fully done: g_mu1 valid

    #pragma unroll
    for (int n2 = 0; n2 < NH; n2++) {
        const int r = n2 * 2 + h;
        sT[d * STR + r] = g_mu1[(base + r) * CC + d];
    }
    __syncthreads();

    uint64_t acc[2][4];
    #pragma unroll
    for (int g = 0; g < 2; g++)
        #pragma unroll
        for (int m = 0; m < 4; m++) acc[g][m] = 0ull;

    for (int kt = 0; kt < K3T; kt++) {
        CP_WAIT0();
        __syncthreads();
        if (kt + 1 < K3T) {
            const float* src = Wmix + (kt + 1) * K3R * 2 * CC;
            uint32_t dstb = ((kt + 1) & 1) ? swb1 : swb0;
            #pragma unroll
            for (int t = tid; t < K3R * 2 * CC / 4; t += 256)
                cpa16(dstb + t * 16, src + t * 4);
            CP_COMMIT();
        }
        const float* sWt = sW[kt & 1];
        #pragma unroll
        for (int r = 0; r < K3R; r++) {
            const int k = kt * K3R + r;
            uint64_t w0 = bcast2(sWt[r * 2 * CC + 0 * CC + d]);
            uint64_t w1 = bcast2(sWt[r * 2 * CC + 1 * CC + d]);
            const ulonglong2* row = reinterpret_cast<const ulonglong2*>(&sT[k * STR + h * NH]);
            ulonglong2 v0 = row[0], v1 = row[1];
            fma2(acc[0][0], v0.x, w0); fma2(acc[0][1], v0.y, w0);
            fma2(acc[0][2], v1.x, w0); fma2(acc[0][3], v1.y, w0);
            fma2(acc[1][0], v0.x, w1); fma2(acc[1][1], v0.y, w1);
            fma2(acc[1][2], v1.x, w1); fma2(acc[1][3], v1.y, w1);
        }
    }
    #pragma unroll
    for (int g = 0; g < 2; g++) {
        float* dst = (g == 0) ? g_muV : g_muW;
        #pragma unroll
        for (int m = 0; m < 4; m++) {
            float2 p = unpk(acc[g][m]);
            dst[(base + h * NH + 2*m)     * CC + d] = p.x;
            dst[(base + h * NH + 2*m + 1) * CC + d] = p.y;
        }
    }
}

// ============================================================================
// K3b: mixing MLP + final outputs. (R11 shape + PDL preamble)
// ============================================================================
#define K4R1 16
#define K4T1 (2 * CC / K4R1)
#define K4R2 8
#define K4T2 (CC / K4R2)

__global__ __launch_bounds__(256) void k_mixout(
    const float* __restrict__ Wm1, const float* __restrict__ bm1,
    const float* __restrict__ Wm2, const float* __restrict__ bm2,
    float* __restrict__ out_q, float* __restrict__ out_mu)
{
    __shared__ __align__(16) float buf[2 * CC * STR];
    __shared__ __align__(16) float sscal[NPB * CC];
    __shared__ __align__(16) float sW[2][3 * CC * K4R2];
    const int tid  = threadIdx.x;
    const int d    = tid & 127;
    const int h    = tid >> 7;
    const int base = blockIdx.x * NPB;
    const uint32_t swb0 = (uint32_t)__cvta_generic_to_shared(sW[0]);
    const uint32_t swb1 = (uint32_t)__cvta_generic_to_shared(sW[1]);

    PDL_TRIGGER();
    #pragma unroll
    for (int t = tid; t < K4R1 * CC / 4; t += 256)
        cpa16(swb0 + t * 16, Wm1 + t * 4);
    CP_COMMIT();
    PDL_WAIT();   // k_mumix fully done: g_muV/g_muW valid

    #pragma unroll
    for (int n2 = 0; n2 < NH; n2++) {
        const int n = n2 * 2 + h;
        const int node = base + n;
        float q1v = g_q1[node * CC + d];
        float v0 = g_muV[(node * 3 + 0) * CC + d];
        float v1 = g_muV[(node * 3 + 1) * CC + d];
        float v2 = g_muV[(node * 3 + 2) * CC + d];
        float w0 = g_muW[(node * 3 + 0) * CC + d];
        float w1 = g_muW[(node * 3 + 1) * CC + d];
        float w2 = g_muW[(node * 3 + 2) * CC + d];
        float vn = sqrtf(fmaf(v0, v0, fmaf(v1, v1, fmaf(v2, v2, EPS_F))));
        sscal[n * CC + d] = fmaf(v0, w0, fmaf(v1, w1, v2 * w2));
        buf[d * STR + n] = q1v;
        buf[(CC + d) * STR + n] = vn;
    }
    __syncthreads();

    // ---- layer 1: hidden = silu(ctx @ Wm1 + bm1) ----
    uint64_t acc[4];
    {
        float bb = bm1[d];
        uint64_t bi = pk(bb, bb);
        #pragma unroll
        for (int m = 0; m < 4; m++) acc[m] = bi;

        for (int kt = 0; kt < K4T1; kt++) {
            CP_WAIT0();
            __syncthreads();
            if (kt + 1 < K4T1) {
                const float* src = Wm1 + (kt + 1) * K4R1 * CC;
                uint32_t dstb = ((kt + 1) & 1) ? swb1 : swb0;
                #pragma unroll
                for (int t = tid; t < K4R1 * CC / 4; t += 256)
                    cpa16(dstb + t * 16, src + t * 4);
                CP_COMMIT();
            }
            const float* sWt = sW[kt & 1];
            #pragma unroll
            for (int r = 0; r < K4R1; r++) {
                const int k = kt * K4R1 + r;
                uint64_t ww = bcast2(sWt[r * CC + d]);
                const ulonglong2* row = reinterpret_cast<const ulonglong2*>(&buf[k * STR + h * NH]);
                ulonglong2 v0 = row[0], v1 = row[1];
                fma2(acc[0], v0.x, ww); fma2(acc[1], v0.y, ww);
                fma2(acc[2], v1.x, ww); fma2(acc[3], v1.y, ww);
            }
        }
    }
    __syncthreads();
    #pragma unroll
    for (int m = 0; m < 4; m++) {
        float2 p = unpk(acc[m]);
        buf[(CC + d) * STR + h * NH + 2*m]     = siluf(p.x);
        buf[(CC + d) * STR + h * NH + 2*m + 1] = siluf(p.y);
    }
    __syncthreads();

    // ---- layer 2: 3 output groups fused ----
    uint64_t a[3][4];
    #pragma unroll
    for (int g = 0; g < 3; g++) {
        float bb = bm2[g * CC + d];
        uint64_t bi = pk(bb, bb);
        #pragma unroll
        for (int m = 0; m < 4; m++) a[g][m] = bi;
    }
    #pragma unroll
    for (int t = tid; t < K4R2 * 3 * CC / 4; t += 256)
        cpa16(swb0 + t * 16, Wm2 + t * 4);
    CP_COMMIT();

    for (int kt = 0; kt < K4T2; kt++) {
        CP_WAIT0();
        __syncthreads();
        if (kt + 1 < K4T2) {
            const float* src = Wm2 + (kt + 1) * K4R2 * 3 * CC;
            uint32_t dstb = ((kt + 1) & 1) ? swb1 : swb0;
            #pragma unroll
            for (int t = tid; t < K4R2 * 3 * CC / 4; t += 256)
                cpa16(dstb + t * 16, src + t * 4);
            CP_COMMIT();
        }
        const float* sWt = sW[kt & 1];
        #pragma unroll
        for (int r = 0; r < K4R2; r++) {
            const int k = kt * K4R2 + r;
            uint64_t w0 = bcast2(sWt[r * 3 * CC + 0 * CC + d]);
            uint64_t w1 = bcast2(sWt[r * 3 * CC + 1 * CC + d]);
            uint64_t w2 = bcast2(sWt[r * 3 * CC + 2 * CC + d]);
            const ulonglong2* row = reinterpret_cast<const ulonglong2*>(&buf[(CC + k) * STR + h * NH]);
            ulonglong2 v0 = row[0], v1 = row[1];
            fma2(a[0][0], v0.x, w0); fma2(a[0][1], v0.y, w0);
            fma2(a[0][2], v1.x, w0); fma2(a[0][3], v1.y, w0);
            fma2(a[1][0], v0.x, w1); fma2(a[1][1], v0.y, w1);
            fma2(a[1][2], v1.x, w1); fma2(a[1][3], v1.y, w1);
            fma2(a[2][0], v0.x, w2); fma2(a[2][1], v0.y, w2);
            fma2(a[2][2], v1.x, w2); fma2(a[2][3], v1.y, w2);
        }
    }

    #pragma unroll
    for (int m = 0; m < 4; m++) {
        float2 p0 = unpk(a[0][m]);
        float2 p1 = unpk(a[1][m]);
        float2 p2 = unpk(a[2][m]);
        #pragma unroll
        for (int t = 0; t < 2; t++) {
            const int n = h * NH + 2*m + t;
            const int node = base + n;
            float y0 = t ? p0.y : p0.x;
            float y1 = t ? p1.y : p1.x;
            float y2 = t ? p2.y : p2.x;
            float q1v  = buf[d * STR + n];
            float scal = sscal[n * CC + d];
            out_q[node * CC + d] = q1v + y0 + y2 * scal;
            #pragma unroll
            for (int v = 0; v < 3; v++) {
                float mw = g_muW[(node * 3 + v) * CC + d];
                float m1 = g_mu1[(node * 3 + v) * CC + d];
                out_mu[(node * 3 + v) * CC + d] = fmaf(y1, mw, m1);
            }
        }
    }
}

// ============================================================================
// Launch with programmatic dependent launch (PDL) edges between all kernels.
// ============================================================================
template <typename... Args>
static inline void launch_pdl(void (*kern)(Args...), dim3 grid, dim3 block,
                              Args... args)
{
    cudaLaunchConfig_t cfg = {};
    cfg.gridDim = grid;
    cfg.blockDim = block;
    cfg.dynamicSmemBytes = 0;
    cfg.stream = 0;
    cudaLaunchAttribute attr[1];
    attr[0].id = cudaLaunchAttributeProgrammaticStreamSerialization;
    attr[0].val.programmaticStreamSerializationAllowed = 1;
    cfg.attrs = attr;
    cfg.numAttrs = 1;
    cudaLaunchKernelEx(&cfg, kern, args...);
}

extern "C" void kernel_launch(void* const* d_in, const int* in_sizes, int n_in,
                              void* d_out, int out_size)
{
    const float* q     = (const float*)d_in[0];
    const float* mu    = (const float*)d_in[1];
    const int*   eidx  = (const int*)  d_in[2];
    const float* ew    = (const float*)d_in[3];
    const float* evs   = (const float*)d_in[4];
    const float* attrs = (const float*)d_in[5];
    const float* Wf    = (const float*)d_in[6];
    const float* bf    = (const float*)d_in[7];
    const float* W1    = (const float*)d_in[8];
    const float* b1    = (const float*)d_in[9];
    const float* W2    = (const float*)d_in[10];
    const float* b2    = (const float*)d_in[11];
    const float* Wmix  = (const float*)d_in[12];
    const float* Wm1   = (const float*)d_in[13];
    const float* bm1   = (const float*)d_in[14];
    const float* Wm2   = (const float*)d_in[15];
    const float* bm2   = (const float*)d_in[16];

    float* out_q  = (float*)d_out;
    float* out_mu = out_q + (size_t)NN * CC;

    launch_pdl(k_context, dim3(NN / NPB), dim3(256), q, mu, W1, b1, W2, b2);
    launch_pdl(k_edge, dim3(1184), dim3(256), eidx, ew, evs, attrs, Wf, bf, mu);
    launch_pdl(k_mumix, dim3((3 * NN) / NPB), dim3(256), Wmix);
    launch_pdl(k_mixout, dim3(NN / NPB), dim3(256), Wm1, bm1, Wm2, bm2, out_q, out_mu);
}